// round 6
// baseline (speedup 1.0000x reference)
#include <cuda_runtime.h>
#include <cuda_bf16.h>
#include <cstdint>

#define NMAX 50000
#define EMAX 800000
#define FDIM 128

// ---------------- scratch (static device globals; no allocation) ------------
__device__ __align__(256) float g_h[(size_t)NMAX * FDIM];   // 25.6 MB (GEMM out / AGG in)
__device__ __align__(256) float g_t[(size_t)NMAX * FDIM];   // 25.6 MB (AGG out / next GEMM in)
__device__ float g_dinv[NMAX];
__device__ int   g_hist[NMAX];
__device__ int   g_start[NMAX + 1];
__device__ int   g_fill[NMAX];
__device__ int   g_erow[EMAX];
__device__ float g_enorm[EMAX];
__device__ int   g_bsum[256];
__device__ int   g_done;          // zero-initialized; reset by last scan block
__device__ int   g_is64;
// W split planes, transposed to BT[n][k] bf16 raw bits: [layer][16384]
__device__ unsigned short g_whi[2][FDIM * FDIM];
__device__ unsigned short g_wlo[2][FDIM * FDIM];

// ---------------- helpers ----------------------------------------------------
__device__ __forceinline__ uint32_t smem_u32(const void* p) {
    uint32_t a;
    asm("{ .reg .u64 t; cvta.to.shared.u64 t, %1; cvt.u32.u64 %0, t; }" : "=r"(a) : "l"(p));
    return a;
}
__device__ __forceinline__ void ldm_x4(uint32_t (&r)[4], uint32_t addr) {
    asm volatile("ldmatrix.sync.aligned.m8n8.x4.shared.b16 {%0,%1,%2,%3}, [%4];"
                 : "=r"(r[0]), "=r"(r[1]), "=r"(r[2]), "=r"(r[3]) : "r"(addr));
}
__device__ __forceinline__ void mma_bf16(float (&c)[4], const uint32_t (&a)[4],
                                         const uint32_t b0, const uint32_t b1) {
    asm volatile(
        "mma.sync.aligned.m16n8k16.row.col.f32.bf16.bf16.f32 "
        "{%0,%1,%2,%3}, {%4,%5,%6,%7}, {%8,%9}, {%0,%1,%2,%3};"
        : "+f"(c[0]), "+f"(c[1]), "+f"(c[2]), "+f"(c[3])
        : "r"(a[0]), "r"(a[1]), "r"(a[2]), "r"(a[3]), "r"(b0), "r"(b1));
}

__device__ __forceinline__ int edge_at(const void* ep, long long idx) {
    return g_is64 ? (int)((const long long*)ep)[idx] : ((const int*)ep)[idx];
}

// ---------------- fused prep: detect (b0) | hist zero | W split --------------
// grid = 1 + nbHist + 128 blocks of 256 threads
__global__ void prep_all(const int* __restrict__ ew, int E, int n, int nbHist,
                         const float* __restrict__ W1, const float* __restrict__ W2) {
    int b = blockIdx.x;
    if (b == 0) {
        // dtype detect: int64 -> odd 32-bit words all zero (node ids < 2^31)
        __shared__ int any;
        if (threadIdx.x == 0) any = 0;
        __syncthreads();
        int words = 2 * E; if (words > 4096) words = 4096;
        int local = 0;
        for (int i = 1 + 2 * (int)threadIdx.x; i < words; i += 2 * blockDim.x)
            local |= ew[i];
        if (local) atomicOr(&any, 1);
        __syncthreads();
        if (threadIdx.x == 0) g_is64 = (any == 0) ? 1 : 0;
    } else if (b <= nbHist) {
        int i = (b - 1) * blockDim.x + threadIdx.x;
        if (i < n) g_hist[i] = 0;
    } else {
        // W transpose + bf16 split: 128 blocks cover 2*128*128 entries
        int idx = (b - 1 - nbHist) * 256 + threadIdx.x;
        if (idx < 2 * FDIM * FDIM) {
            int m = idx >> 14;
            int r = idx & 16383;
            int k = r >> 7, nn = r & 127;
            float v = (m ? W2 : W1)[k * FDIM + nn];
            __nv_bfloat16 hi = __float2bfloat16(v);
            __nv_bfloat16 lo = __float2bfloat16(v - __bfloat162float(hi));
            g_whi[m][nn * FDIM + k] = __bfloat16_as_ushort(hi);
            g_wlo[m][nn * FDIM + k] = __bfloat16_as_ushort(lo);
        }
    }
}

__global__ void hist_count(const void* __restrict__ ep, int E) {
    int e = blockIdx.x * blockDim.x + threadIdx.x;
    if (e >= E) return;
    atomicAdd(&g_hist[edge_at(ep, (long long)E + e)], 1);
}

// ---------------- scan: pass1 + last-block serial scan of block sums --------
__global__ void scan12(int n, int nb) {
    __shared__ int s[512];
    __shared__ int amLast;
    int i = blockIdx.x * 512 + threadIdx.x;
    s[threadIdx.x] = (i < n) ? g_hist[i] : 0;
    __syncthreads();
    for (int off = 256; off > 0; off >>= 1) {
        if (threadIdx.x < off) s[threadIdx.x] += s[threadIdx.x + off];
        __syncthreads();
    }
    if (threadIdx.x == 0) {
        g_bsum[blockIdx.x] = s[0];
        __threadfence();
        amLast = (atomicAdd(&g_done, 1) == nb - 1) ? 1 : 0;
    }
    __syncthreads();
    if (amLast && threadIdx.x == 0) {
        int acc = 0;
        for (int k = 0; k < nb; k++) { int v = g_bsum[k]; g_bsum[k] = acc; acc += v; }
        g_start[n] = acc;
        g_done = 0;                      // reset for next replay (deterministic)
    }
}

// ---------------- scan finish + dinv + fill seed -----------------------------
__global__ void scan3_dinv(int n) {
    __shared__ int s[512];
    int i = blockIdx.x * 512 + threadIdx.x;
    int v = (i < n) ? g_hist[i] : 0;
    s[threadIdx.x] = v;
    __syncthreads();
    for (int off = 1; off < 512; off <<= 1) {
        int t = (threadIdx.x >= off) ? s[threadIdx.x - off] : 0;
        __syncthreads();
        s[threadIdx.x] += t;
        __syncthreads();
    }
    if (i < n) {
        int ex = s[threadIdx.x] - v + g_bsum[blockIdx.x];
        g_start[i] = ex;
        g_fill[i]  = ex;
        g_dinv[i]  = rsqrtf((float)(v + 1));   // deg incl. self-loop
    }
}

// ---------------- CSR fill --------------------------------------------------
__global__ void fill_edges(const void* __restrict__ ep, int E) {
    int e = blockIdx.x * blockDim.x + threadIdx.x;
    if (e >= E) return;
    int r = edge_at(ep, e);
    int c = edge_at(ep, (long long)E + e);
    int pos = atomicAdd(&g_fill[c], 1);
    g_erow[pos]  = r;
    g_enorm[pos] = g_dinv[r] * g_dinv[c];
}

// ---------------- mma.sync GEMM: g_h[M,128] = A[M,128] @ W ------------------
// Split-bf16 (hi/lo), 3 HMMA terms, fp32 accumulate.
#define TROW 272                      // padded row stride in bytes (136 bf16)
#define PL_BYTES (128 * TROW)         // 34816 per plane
#define SMEM_GEMM (4 * PL_BYTES)      // 139264

__global__ __launch_bounds__(256, 1)
void gemm_mma(const float* __restrict__ Aparam, int use_gt, int layer, int M) {
    extern __shared__ char smem[];
    uint32_t sbase = smem_u32(smem);
    uint32_t sAhi = sbase;
    uint32_t sAlo = sbase + PL_BYTES;
    uint32_t sBhi = sbase + 2 * PL_BYTES;
    uint32_t sBlo = sbase + 3 * PL_BYTES;

    int tid  = threadIdx.x;
    int wid  = tid >> 5;
    int lane = tid & 31;
    int row0 = blockIdx.x * 128;
    const float* A = use_gt ? (const float*)g_t : Aparam;
    const unsigned short* WH = g_whi[layer];
    const unsigned short* WL = g_wlo[layer];

    // ---- fill smem: 4096 slots = (row 0..127) x (k4 0..31) ----
#pragma unroll 4
    for (int it = 0; it < 16; it++) {
        int slot = tid + it * 256;
        int r  = slot >> 5;
        int k  = (slot & 31) * 4;
        uint32_t off = (uint32_t)(r * TROW + k * 2);

        float4 v = make_float4(0.f, 0.f, 0.f, 0.f);
        int gr = row0 + r;
        if (gr < M) v = *(const float4*)(A + (size_t)gr * 128 + k);
        __nv_bfloat16 h0 = __float2bfloat16(v.x), h1 = __float2bfloat16(v.y);
        __nv_bfloat16 h2 = __float2bfloat16(v.z), h3 = __float2bfloat16(v.w);
        __nv_bfloat16 l0 = __float2bfloat16(v.x - __bfloat162float(h0));
        __nv_bfloat16 l1 = __float2bfloat16(v.y - __bfloat162float(h1));
        __nv_bfloat16 l2 = __float2bfloat16(v.z - __bfloat162float(h2));
        __nv_bfloat16 l3 = __float2bfloat16(v.w - __bfloat162float(h3));
        uint2 hA = make_uint2(((uint32_t)__bfloat16_as_ushort(h1) << 16) | __bfloat16_as_ushort(h0),
                              ((uint32_t)__bfloat16_as_ushort(h3) << 16) | __bfloat16_as_ushort(h2));
        uint2 lA = make_uint2(((uint32_t)__bfloat16_as_ushort(l1) << 16) | __bfloat16_as_ushort(l0),
                              ((uint32_t)__bfloat16_as_ushort(l3) << 16) | __bfloat16_as_ushort(l2));
        *(uint2*)(smem + off) = hA;
        *(uint2*)(smem + PL_BYTES + off) = lA;

        *(uint2*)(smem + 2 * PL_BYTES + off) = *(const uint2*)(WH + r * 128 + k);
        *(uint2*)(smem + 3 * PL_BYTES + off) = *(const uint2*)(WL + r * 128 + k);
    }
    __syncthreads();

    // ---- warp tiles: 4 m-groups x 2 n-groups; warp = 32 rows x 64 cols ----
    int m0 = (wid & 3) * 32;
    int n0 = (wid >> 2) * 64;
    int arow  = lane & 15;
    int acol  = (lane >> 4) << 3;
    int l7    = lane & 7;
    int halfq = lane >> 3;
    int bn    = ((halfq >> 1) << 3) + l7;
    int bk    = (halfq & 1) << 3;

    float c[2][8][4];
#pragma unroll
    for (int mt = 0; mt < 2; mt++)
#pragma unroll
        for (int j = 0; j < 8; j++)
#pragma unroll
            for (int q = 0; q < 4; q++) c[mt][j][q] = 0.f;

#pragma unroll
    for (int kc = 0; kc < 8; kc++) {
        int k0 = kc * 16;
        uint32_t ahi[2][4], alo[2][4];
#pragma unroll
        for (int mt = 0; mt < 2; mt++) {
            uint32_t off = (uint32_t)((m0 + mt * 16 + arow) * TROW + (k0 + acol) * 2);
            ldm_x4(ahi[mt], sAhi + off);
            ldm_x4(alo[mt], sAlo + off);
        }
        uint32_t bhi[8][2], blo[8][2];
#pragma unroll
        for (int jp = 0; jp < 4; jp++) {
            uint32_t off = (uint32_t)((n0 + jp * 16 + bn) * TROW + (k0 + bk) * 2);
            uint32_t r4[4];
            ldm_x4(r4, sBhi + off);
            bhi[jp * 2][0] = r4[0]; bhi[jp * 2][1] = r4[1];
            bhi[jp * 2 + 1][0] = r4[2]; bhi[jp * 2 + 1][1] = r4[3];
            ldm_x4(r4, sBlo + off);
            blo[jp * 2][0] = r4[0]; blo[jp * 2][1] = r4[1];
            blo[jp * 2 + 1][0] = r4[2]; blo[jp * 2 + 1][1] = r4[3];
        }
#pragma unroll
        for (int mt = 0; mt < 2; mt++)
#pragma unroll
            for (int j = 0; j < 8; j++) {
                mma_bf16(c[mt][j], ahi[mt], bhi[j][0], bhi[j][1]);
                mma_bf16(c[mt][j], alo[mt], bhi[j][0], bhi[j][1]);
                mma_bf16(c[mt][j], ahi[mt], blo[j][0], blo[j][1]);
            }
    }

    int g = lane >> 2, t = lane & 3;
#pragma unroll
    for (int mt = 0; mt < 2; mt++) {
        int rlo = row0 + m0 + mt * 16 + g;
#pragma unroll
        for (int j = 0; j < 8; j++) {
            int col = n0 + j * 8 + t * 2;
            if (rlo < M)
                *(float2*)(g_h + (size_t)rlo * 128 + col) = make_float2(c[mt][j][0], c[mt][j][1]);
            if (rlo + 8 < M)
                *(float2*)(g_h + (size_t)(rlo + 8) * 128 + col) = make_float2(c[mt][j][2], c[mt][j][3]);
        }
    }
}

// ---------------- aggregation core (warp per node) --------------------------
__device__ __forceinline__ float4 agg_node(int gw, int lane) {
    const float4* base = (const float4*)g_h;
    float di = g_dinv[gw];
    float w0 = di * di;
    float4 v = __ldg(&base[(size_t)gw * 32 + lane]);
    float4 acc = make_float4(w0 * v.x, w0 * v.y, w0 * v.z, w0 * v.w);
    int e = g_start[gw], t = g_start[gw + 1];
    for (; e + 3 < t; e += 4) {
        int   r0 = g_erow[e],   r1 = g_erow[e+1], r2 = g_erow[e+2], r3 = g_erow[e+3];
        float n0 = g_enorm[e],  n1 = g_enorm[e+1], n2 = g_enorm[e+2], n3 = g_enorm[e+3];
        float4 u0 = __ldg(&base[(size_t)r0 * 32 + lane]);
        float4 u1 = __ldg(&base[(size_t)r1 * 32 + lane]);
        float4 u2 = __ldg(&base[(size_t)r2 * 32 + lane]);
        float4 u3 = __ldg(&base[(size_t)r3 * 32 + lane]);
        acc.x += n0*u0.x + n1*u1.x + n2*u2.x + n3*u3.x;
        acc.y += n0*u0.y + n1*u1.y + n2*u2.y + n3*u3.y;
        acc.z += n0*u0.z + n1*u1.z + n2*u2.z + n3*u3.z;
        acc.w += n0*u0.w + n1*u1.w + n2*u2.w + n3*u3.w;
    }
    for (; e < t; e++) {
        int r = g_erow[e]; float w = g_enorm[e];
        float4 u = __ldg(&base[(size_t)r * 32 + lane]);
        acc.x += w*u.x; acc.y += w*u.y; acc.z += w*u.z; acc.w += w*u.w;
    }
    return acc;
}

// layer-1 agg: g_h -> g_t (+b1)
__global__ void agg_kernel(const float* __restrict__ bias, int n) {
    int gw   = (blockIdx.x * blockDim.x + threadIdx.x) >> 5;
    int lane = threadIdx.x & 31;
    if (gw >= n) return;
    float4 acc = agg_node(gw, lane);
    float4 b = __ldg(&((const float4*)bias)[lane]);
    acc.x += b.x; acc.y += b.y; acc.z += b.z; acc.w += b.w;
    ((float4*)g_t)[(size_t)gw * 32 + lane] = acc;
}

// layer-2 agg fused with FC: g_h -> out[N,8]   (skips g_t round trip)
__global__ void agg_fc_kernel(const float* __restrict__ b2,
                              const float* __restrict__ Wfc,
                              const float* __restrict__ bfc,
                              float* __restrict__ out, int n) {
    __shared__ float ws[128 * 8];
    __shared__ float bs[8];
    for (int i = threadIdx.x; i < 1024; i += blockDim.x) ws[i] = Wfc[i];
    if (threadIdx.x < 8) bs[threadIdx.x] = bfc[threadIdx.x];
    __syncthreads();
    int gw   = (blockIdx.x * blockDim.x + threadIdx.x) >> 5;
    int lane = threadIdx.x & 31;
    if (gw >= n) return;
    float4 acc = agg_node(gw, lane);
    float4 b = __ldg(&((const float4*)b2)[lane]);
    acc.x += b.x; acc.y += b.y; acc.z += b.z; acc.w += b.w;
    // FC: out_c = sum_k acc_k * Wfc[k][c]
    int k0 = lane * 4;
#pragma unroll
    for (int c = 0; c < 8; c++) {
        float p = acc.x * ws[(k0 + 0) * 8 + c] + acc.y * ws[(k0 + 1) * 8 + c]
                + acc.z * ws[(k0 + 2) * 8 + c] + acc.w * ws[(k0 + 3) * 8 + c];
#pragma unroll
        for (int off = 16; off > 0; off >>= 1)
            p += __shfl_xor_sync(0xffffffffu, p, off);
        if (lane == 0) out[(size_t)gw * 8 + c] = p + bs[c];
    }
}

// ---------------- launch ----------------------------------------------------
extern "C" void kernel_launch(void* const* d_in, const int* in_sizes, int n_in,
                              void* d_out, int out_size) {
    const float* x   = (const float*)d_in[0];
    const void*  ei  = d_in[1];
    const float* W1  = (const float*)d_in[2];
    const float* b1  = (const float*)d_in[3];
    const float* W2  = (const float*)d_in[4];
    const float* b2  = (const float*)d_in[5];
    const float* Wfc = (const float*)d_in[6];
    const float* bfc = (const float*)d_in[7];
    float* out = (float*)d_out;

    int N = in_sizes[0] / FDIM;
    int E = in_sizes[1] / 2;
    int nb = (N + 511) / 512;

    int tB = 256;
    int gN = (N + tB - 1) / tB;
    int gE = (E + tB - 1) / tB;
    int gW = (N * 32 + tB - 1) / tB;
    int gM = (N + 127) / 128;

    cudaFuncSetAttribute(gemm_mma, cudaFuncAttributeMaxDynamicSharedMemorySize, SMEM_GEMM);

    prep_all<<<1 + gN + 128, tB>>>((const int*)ei, E, N, gN, W1, W2);
    hist_count<<<gE, tB>>>(ei, E);
    scan12<<<nb, 512>>>(N, nb);
    scan3_dinv<<<nb, 512>>>(N);
    fill_edges<<<gE, tB>>>(ei, E);

    gemm_mma<<<gM, 256, SMEM_GEMM>>>(x, 0, 0, N);        // x @ W1 -> g_h
    agg_kernel<<<gW, tB>>>(b1, N);                       // g_h -> g_t (+b1)
    gemm_mma<<<gM, 256, SMEM_GEMM>>>(nullptr, 1, 1, N);  // g_t @ W2 -> g_h
    agg_fc_kernel<<<gW, tB>>>(b2, Wfc, bfc, out, N);     // g_h -> out (agg+FC)
}

// round 9
// speedup vs baseline: 1.2324x; 1.2324x over previous
#include <cuda_runtime.h>
#include <cuda_bf16.h>
#include <cstdint>

#define NMAX 50000
#define EMAX 800000
#define FDIM 128

// ---------------- scratch (static device globals; no allocation) ------------
__device__ __align__(256) float g_h[(size_t)NMAX * FDIM];   // 25.6 MB (GEMM out / AGG in)
__device__ __align__(256) float g_t[(size_t)NMAX * FDIM];   // 25.6 MB (AGG out / next GEMM in)
__device__ float g_dinv[NMAX];
__device__ int   g_hist[NMAX];
__device__ int   g_start[NMAX + 1];
__device__ int   g_fill[NMAX];
__device__ int   g_erow[EMAX];
__device__ float g_enorm[EMAX];
__device__ int   g_bsum[256];
__device__ int   g_done;          // zero-initialized; reset by last scan block
__device__ int   g_is64;
// W split planes, transposed to BT[n][k] bf16 raw bits: [layer][16384]
__device__ unsigned short g_whi[2][FDIM * FDIM];
__device__ unsigned short g_wlo[2][FDIM * FDIM];

// ---------------- helpers ----------------------------------------------------
__device__ __forceinline__ uint32_t smem_u32(const void* p) {
    uint32_t a;
    asm("{ .reg .u64 t; cvta.to.shared.u64 t, %1; cvt.u32.u64 %0, t; }" : "=r"(a) : "l"(p));
    return a;
}
__device__ __forceinline__ void ldm_x4(uint32_t (&r)[4], uint32_t addr) {
    asm volatile("ldmatrix.sync.aligned.m8n8.x4.shared.b16 {%0,%1,%2,%3}, [%4];"
                 : "=r"(r[0]), "=r"(r[1]), "=r"(r[2]), "=r"(r[3]) : "r"(addr));
}
__device__ __forceinline__ void mma_bf16(float (&c)[4], const uint32_t (&a)[4],
                                         const uint32_t b0, const uint32_t b1) {
    asm volatile(
        "mma.sync.aligned.m16n8k16.row.col.f32.bf16.bf16.f32 "
        "{%0,%1,%2,%3}, {%4,%5,%6,%7}, {%8,%9}, {%0,%1,%2,%3};"
        : "+f"(c[0]), "+f"(c[1]), "+f"(c[2]), "+f"(c[3])
        : "r"(a[0]), "r"(a[1]), "r"(a[2]), "r"(a[3]), "r"(b0), "r"(b1));
}

__device__ __forceinline__ int edge_at(const void* ep, long long idx) {
    return g_is64 ? (int)((const long long*)ep)[idx] : ((const int*)ep)[idx];
}

// ---------------- fused prep: detect (b0) | hist zero | W split --------------
// grid = 1 + nbHist + 128 blocks of 256 threads
__global__ void prep_all(const int* __restrict__ ew, int E, int n, int nbHist,
                         const float* __restrict__ W1, const float* __restrict__ W2) {
    int b = blockIdx.x;
    if (b == 0) {
        // dtype detect: int64 -> odd 32-bit words all zero (node ids < 2^31)
        __shared__ int any;
        if (threadIdx.x == 0) any = 0;
        __syncthreads();
        int words = 2 * E; if (words > 4096) words = 4096;
        int local = 0;
        for (int i = 1 + 2 * (int)threadIdx.x; i < words; i += 2 * blockDim.x)
            local |= ew[i];
        if (local) atomicOr(&any, 1);
        __syncthreads();
        if (threadIdx.x == 0) g_is64 = (any == 0) ? 1 : 0;
    } else if (b <= nbHist) {
        int i = (b - 1) * blockDim.x + threadIdx.x;
        if (i < n) g_hist[i] = 0;
    } else {
        // W transpose + bf16 split: 128 blocks cover 2*128*128 entries
        int idx = (b - 1 - nbHist) * 256 + threadIdx.x;
        if (idx < 2 * FDIM * FDIM) {
            int m = idx >> 14;
            int r = idx & 16383;
            int k = r >> 7, nn = r & 127;
            float v = (m ? W2 : W1)[k * FDIM + nn];
            __nv_bfloat16 hi = __float2bfloat16(v);
            __nv_bfloat16 lo = __float2bfloat16(v - __bfloat162float(hi));
            g_whi[m][nn * FDIM + k] = __bfloat16_as_ushort(hi);
            g_wlo[m][nn * FDIM + k] = __bfloat16_as_ushort(lo);
        }
    }
}

__global__ void hist_count(const void* __restrict__ ep, int E) {
    int e = blockIdx.x * blockDim.x + threadIdx.x;
    if (e >= E) return;
    atomicAdd(&g_hist[edge_at(ep, (long long)E + e)], 1);
}

// ---------------- scan: pass1 + last-block serial scan of block sums --------
__global__ void scan12(int n, int nb) {
    __shared__ int s[512];
    __shared__ int amLast;
    int i = blockIdx.x * 512 + threadIdx.x;
    s[threadIdx.x] = (i < n) ? g_hist[i] : 0;
    __syncthreads();
    for (int off = 256; off > 0; off >>= 1) {
        if (threadIdx.x < off) s[threadIdx.x] += s[threadIdx.x + off];
        __syncthreads();
    }
    if (threadIdx.x == 0) {
        g_bsum[blockIdx.x] = s[0];
        __threadfence();
        amLast = (atomicAdd(&g_done, 1) == nb - 1) ? 1 : 0;
    }
    __syncthreads();
    if (amLast && threadIdx.x == 0) {
        int acc = 0;
        for (int k = 0; k < nb; k++) { int v = g_bsum[k]; g_bsum[k] = acc; acc += v; }
        g_start[n] = acc;
        g_done = 0;                      // reset for next replay (deterministic)
    }
}

// ---------------- scan finish + dinv + fill seed -----------------------------
__global__ void scan3_dinv(int n) {
    __shared__ int s[512];
    int i = blockIdx.x * 512 + threadIdx.x;
    int v = (i < n) ? g_hist[i] : 0;
    s[threadIdx.x] = v;
    __syncthreads();
    for (int off = 1; off < 512; off <<= 1) {
        int t = (threadIdx.x >= off) ? s[threadIdx.x - off] : 0;
        __syncthreads();
        s[threadIdx.x] += t;
        __syncthreads();
    }
    if (i < n) {
        int ex = s[threadIdx.x] - v + g_bsum[blockIdx.x];
        g_start[i] = ex;
        g_fill[i]  = ex;
        g_dinv[i]  = rsqrtf((float)(v + 1));   // deg incl. self-loop
    }
}

// ---------------- CSR fill --------------------------------------------------
__global__ void fill_edges(const void* __restrict__ ep, int E) {
    int e = blockIdx.x * blockDim.x + threadIdx.x;
    if (e >= E) return;
    int r = edge_at(ep, e);
    int c = edge_at(ep, (long long)E + e);
    int pos = atomicAdd(&g_fill[c], 1);
    g_erow[pos]  = r;
    g_enorm[pos] = g_dinv[r] * g_dinv[c];
}

// ---------------- mma.sync GEMM: g_h[M,128] = A[M,128] @ W ------------------
// Split-bf16 (hi/lo), 3 HMMA terms, fp32 accumulate.
#define TROW 272                      // padded row stride in bytes (136 bf16)
#define PL_BYTES (128 * TROW)         // 34816 per plane
#define SMEM_GEMM (4 * PL_BYTES)      // 139264

__global__ __launch_bounds__(256, 1)
void gemm_mma(const float* __restrict__ Aparam, int use_gt, int layer, int M) {
    extern __shared__ char smem[];
    uint32_t sbase = smem_u32(smem);
    uint32_t sAhi = sbase;
    uint32_t sAlo = sbase + PL_BYTES;
    uint32_t sBhi = sbase + 2 * PL_BYTES;
    uint32_t sBlo = sbase + 3 * PL_BYTES;

    int tid  = threadIdx.x;
    int wid  = tid >> 5;
    int lane = tid & 31;
    int row0 = blockIdx.x * 128;
    const float* A = use_gt ? (const float*)g_t : Aparam;
    const unsigned short* WH = g_whi[layer];
    const unsigned short* WL = g_wlo[layer];

    // ---- fill smem: 4096 slots = (row 0..127) x (k4 0..31) ----
#pragma unroll 4
    for (int it = 0; it < 16; it++) {
        int slot = tid + it * 256;
        int r  = slot >> 5;
        int k  = (slot & 31) * 4;
        uint32_t off = (uint32_t)(r * TROW + k * 2);

        float4 v = make_float4(0.f, 0.f, 0.f, 0.f);
        int gr = row0 + r;
        if (gr < M) v = *(const float4*)(A + (size_t)gr * 128 + k);
        __nv_bfloat16 h0 = __float2bfloat16(v.x), h1 = __float2bfloat16(v.y);
        __nv_bfloat16 h2 = __float2bfloat16(v.z), h3 = __float2bfloat16(v.w);
        __nv_bfloat16 l0 = __float2bfloat16(v.x - __bfloat162float(h0));
        __nv_bfloat16 l1 = __float2bfloat16(v.y - __bfloat162float(h1));
        __nv_bfloat16 l2 = __float2bfloat16(v.z - __bfloat162float(h2));
        __nv_bfloat16 l3 = __float2bfloat16(v.w - __bfloat162float(h3));
        uint2 hA = make_uint2(((uint32_t)__bfloat16_as_ushort(h1) << 16) | __bfloat16_as_ushort(h0),
                              ((uint32_t)__bfloat16_as_ushort(h3) << 16) | __bfloat16_as_ushort(h2));
        uint2 lA = make_uint2(((uint32_t)__bfloat16_as_ushort(l1) << 16) | __bfloat16_as_ushort(l0),
                              ((uint32_t)__bfloat16_as_ushort(l3) << 16) | __bfloat16_as_ushort(l2));
        *(uint2*)(smem + off) = hA;
        *(uint2*)(smem + PL_BYTES + off) = lA;

        *(uint2*)(smem + 2 * PL_BYTES + off) = *(const uint2*)(WH + r * 128 + k);
        *(uint2*)(smem + 3 * PL_BYTES + off) = *(const uint2*)(WL + r * 128 + k);
    }
    __syncthreads();

    // ---- warp tiles: 4 m-groups x 2 n-groups; warp = 32 rows x 64 cols ----
    int m0 = (wid & 3) * 32;
    int n0 = (wid >> 2) * 64;
    int arow  = lane & 15;
    int acol  = (lane >> 4) << 3;
    int l7    = lane & 7;
    int halfq = lane >> 3;
    int bn    = ((halfq >> 1) << 3) + l7;
    int bk    = (halfq & 1) << 3;

    float c[2][8][4];
#pragma unroll
    for (int mt = 0; mt < 2; mt++)
#pragma unroll
        for (int j = 0; j < 8; j++)
#pragma unroll
            for (int q = 0; q < 4; q++) c[mt][j][q] = 0.f;

#pragma unroll
    for (int kc = 0; kc < 8; kc++) {
        int k0 = kc * 16;
        uint32_t ahi[2][4], alo[2][4];
#pragma unroll
        for (int mt = 0; mt < 2; mt++) {
            uint32_t off = (uint32_t)((m0 + mt * 16 + arow) * TROW + (k0 + acol) * 2);
            ldm_x4(ahi[mt], sAhi + off);
            ldm_x4(alo[mt], sAlo + off);
        }
        uint32_t bhi[8][2], blo[8][2];
#pragma unroll
        for (int jp = 0; jp < 4; jp++) {
            uint32_t off = (uint32_t)((n0 + jp * 16 + bn) * TROW + (k0 + bk) * 2);
            uint32_t r4[4];
            ldm_x4(r4, sBhi + off);
            bhi[jp * 2][0] = r4[0]; bhi[jp * 2][1] = r4[1];
            bhi[jp * 2 + 1][0] = r4[2]; bhi[jp * 2 + 1][1] = r4[3];
            ldm_x4(r4, sBlo + off);
            blo[jp * 2][0] = r4[0]; blo[jp * 2][1] = r4[1];
            blo[jp * 2 + 1][0] = r4[2]; blo[jp * 2 + 1][1] = r4[3];
        }
#pragma unroll
        for (int mt = 0; mt < 2; mt++)
#pragma unroll
            for (int j = 0; j < 8; j++) {
                mma_bf16(c[mt][j], ahi[mt], bhi[j][0], bhi[j][1]);
                mma_bf16(c[mt][j], alo[mt], bhi[j][0], bhi[j][1]);
                mma_bf16(c[mt][j], ahi[mt], blo[j][0], blo[j][1]);
            }
    }

    int g = lane >> 2, t = lane & 3;
#pragma unroll
    for (int mt = 0; mt < 2; mt++) {
        int rlo = row0 + m0 + mt * 16 + g;
#pragma unroll
        for (int j = 0; j < 8; j++) {
            int col = n0 + j * 8 + t * 2;
            if (rlo < M)
                *(float2*)(g_h + (size_t)rlo * 128 + col) = make_float2(c[mt][j][0], c[mt][j][1]);
            if (rlo + 8 < M)
                *(float2*)(g_h + (size_t)(rlo + 8) * 128 + col) = make_float2(c[mt][j][2], c[mt][j][3]);
        }
    }
}

// ---------------- aggregation core (warp per node) --------------------------
__device__ __forceinline__ float4 agg_node(int gw, int lane) {
    const float4* base = (const float4*)g_h;
    float di = g_dinv[gw];
    float w0 = di * di;
    float4 v = __ldg(&base[(size_t)gw * 32 + lane]);
    float4 acc = make_float4(w0 * v.x, w0 * v.y, w0 * v.z, w0 * v.w);
    int e = g_start[gw], t = g_start[gw + 1];
    for (; e + 3 < t; e += 4) {
        int   r0 = g_erow[e],   r1 = g_erow[e+1], r2 = g_erow[e+2], r3 = g_erow[e+3];
        float n0 = g_enorm[e],  n1 = g_enorm[e+1], n2 = g_enorm[e+2], n3 = g_enorm[e+3];
        float4 u0 = __ldg(&base[(size_t)r0 * 32 + lane]);
        float4 u1 = __ldg(&base[(size_t)r1 * 32 + lane]);
        float4 u2 = __ldg(&base[(size_t)r2 * 32 + lane]);
        float4 u3 = __ldg(&base[(size_t)r3 * 32 + lane]);
        acc.x += n0*u0.x + n1*u1.x + n2*u2.x + n3*u3.x;
        acc.y += n0*u0.y + n1*u1.y + n2*u2.y + n3*u3.y;
        acc.z += n0*u0.z + n1*u1.z + n2*u2.z + n3*u3.z;
        acc.w += n0*u0.w + n1*u1.w + n2*u2.w + n3*u3.w;
    }
    for (; e < t; e++) {
        int r = g_erow[e]; float w = g_enorm[e];
        float4 u = __ldg(&base[(size_t)r * 32 + lane]);
        acc.x += w*u.x; acc.y += w*u.y; acc.z += w*u.z; acc.w += w*u.w;
    }
    return acc;
}

// layer-1 agg: g_h -> g_t (+b1)
__global__ void agg_kernel(const float* __restrict__ bias, int n) {
    int gw   = (blockIdx.x * blockDim.x + threadIdx.x) >> 5;
    int lane = threadIdx.x & 31;
    if (gw >= n) return;
    float4 acc = agg_node(gw, lane);
    float4 b = __ldg(&((const float4*)bias)[lane]);
    acc.x += b.x; acc.y += b.y; acc.z += b.z; acc.w += b.w;
    ((float4*)g_t)[(size_t)gw * 32 + lane] = acc;
}

// layer-2 agg fused with FC: g_h -> out[N,8]   (skips g_t round trip)
// Weight layout TRANSPOSED in smem (wsT[c*128+k]) so each lane reads a
// float4 at wsT[c*128 + lane*4] -> conflict-free LDS.128 (R6 regression fix).
__global__ void agg_fc_kernel(const float* __restrict__ b2,
                              const float* __restrict__ Wfc,
                              const float* __restrict__ bfc,
                              float* __restrict__ out, int n) {
    __shared__ float wsT[8 * 128];
    __shared__ float bs[8];
    for (int i = threadIdx.x; i < 1024; i += blockDim.x) {
        int k = i >> 3, c = i & 7;
        wsT[c * 128 + k] = Wfc[i];
    }
    if (threadIdx.x < 8) bs[threadIdx.x] = bfc[threadIdx.x];
    __syncthreads();
    int gw   = (blockIdx.x * blockDim.x + threadIdx.x) >> 5;
    int lane = threadIdx.x & 31;
    if (gw >= n) return;
    float4 acc = agg_node(gw, lane);
    float4 b = __ldg(&((const float4*)b2)[lane]);
    acc.x += b.x; acc.y += b.y; acc.z += b.z; acc.w += b.w;
#pragma unroll
    for (int c = 0; c < 8; c++) {
        float4 w = *(const float4*)&wsT[c * 128 + lane * 4];
        float p = acc.x * w.x + acc.y * w.y + acc.z * w.z + acc.w * w.w;
#pragma unroll
        for (int off = 16; off > 0; off >>= 1)
            p += __shfl_xor_sync(0xffffffffu, p, off);
        if (lane == 0) out[(size_t)gw * 8 + c] = p + bs[c];
    }
}

// ---------------- launch ----------------------------------------------------
extern "C" void kernel_launch(void* const* d_in, const int* in_sizes, int n_in,
                              void* d_out, int out_size) {
    const float* x   = (const float*)d_in[0];
    const void*  ei  = d_in[1];
    const float* W1  = (const float*)d_in[2];
    const float* b1  = (const float*)d_in[3];
    const float* W2  = (const float*)d_in[4];
    const float* b2  = (const float*)d_in[5];
    const float* Wfc = (const float*)d_in[6];
    const float* bfc = (const float*)d_in[7];
    float* out = (float*)d_out;

    int N = in_sizes[0] / FDIM;
    int E = in_sizes[1] / 2;
    int nb = (N + 511) / 512;

    int tB = 256;
    int gN = (N + tB - 1) / tB;
    int gE = (E + tB - 1) / tB;
    int gW = (N * 32 + tB - 1) / tB;
    int gM = (N + 127) / 128;

    cudaFuncSetAttribute(gemm_mma, cudaFuncAttributeMaxDynamicSharedMemorySize, SMEM_GEMM);

    prep_all<<<1 + gN + 128, tB>>>((const int*)ei, E, N, gN, W1, W2);
    hist_count<<<gE, tB>>>(ei, E);
    scan12<<<nb, 512>>>(N, nb);
    scan3_dinv<<<nb, 512>>>(N);
    fill_edges<<<gE, tB>>>(ei, E);

    gemm_mma<<<gM, 256, SMEM_GEMM>>>(x, 0, 0, N);        // x @ W1 -> g_h
    agg_kernel<<<gW, tB>>>(b1, N);                       // g_h -> g_t (+b1)
    gemm_mma<<<gM, 256, SMEM_GEMM>>>(nullptr, 1, 1, N);  // g_t @ W2 -> g_h
    agg_fc_kernel<<<gW, tB>>>(b2, Wfc, bfc, out, N);     // g_h -> out (agg+FC)
}